// round 1
// baseline (speedup 1.0000x reference)
#include <cuda_runtime.h>

#define BATCH 4096
#define D0 1024
#define D1 2048
#define D2 2048
#define D3 512
#define NSTEPS 20
#define LRATE 0.1f

// ---------------- device scratch (allocation-free rule: __device__ globals) ----
__device__ float g_r1[BATCH * D1];
__device__ float g_r2[BATCH * D2];
__device__ float g_r3[BATCH * D3];
__device__ float g_e0[BATCH * D0];
__device__ float g_e1[BATCH * D1];
__device__ float g_e2[BATCH * D2];

// ---------------- GEMM config ----------------
constexpr int BM = 128, BN = 128, BK = 16;
constexpr int TM = 8, TN = 8;       // 16x16 threads = 256
constexpr int PAD = 4;

enum { BL_NT = 0, BL_NN = 1 };      // B layout: NT => B is (N,K) row-major; NN => B is (K,N) row-major
enum { EPI_FWD = 0,                 // C = tanh(acc + X[n])            (X = bias, len N)
       EPI_ERR = 1,                 // C = X[m,n] - tanh(acc)          (X = target matrix)
       EPI_UPD = 2,                 // C += LR*(acc - X[m,n])          (X = error matrix, X != C)
       EPI_UPD3 = 3 };              // C = C*(1-LR) + LR*acc           (last layer: err == state)

template <int BLAYOUT, int EPI>
__global__ __launch_bounds__(256, 2)
void gemm_epi(const float* __restrict__ A, const float* __restrict__ B,
              const float* __restrict__ X, float* C,
              int M, int N, int K)
{
    __shared__ __align__(16) float As[2][BK][BM + PAD];
    __shared__ __align__(16) float Bs[2][BK][BN + PAD];

    const int tid = threadIdx.x;
    const int bm = blockIdx.y * BM;
    const int bn = blockIdx.x * BN;

    // A tile (BM x BK): thread loads 2x float4; rows a_row, a_row+64
    const int a_row = tid >> 2;          // 0..63
    const int a_col = (tid & 3) * 4;     // 0,4,8,12
    // NN B tile (BK x BN): rows bn_row, bn_row+8; 32 float4 per row
    const int bnn_row = tid >> 5;        // 0..7
    const int bnn_col = (tid & 31) * 4;  // 0..124

    const int tr = (tid >> 4) * TM;      // output row in tile
    const int tc = (tid & 15) * TN;      // output col in tile

    float acc[TM][TN];
#pragma unroll
    for (int i = 0; i < TM; i++)
#pragma unroll
        for (int j = 0; j < TN; j++) acc[i][j] = 0.0f;

    const int ntiles = K / BK;

    const float* pA = A + (size_t)(bm + a_row) * K + a_col;

    // --- preload tile 0 into smem buffer 0 ---
    {
        float4 v0 = *(const float4*)(pA);
        float4 v1 = *(const float4*)(pA + (size_t)64 * K);
        As[0][a_col + 0][a_row] = v0.x; As[0][a_col + 1][a_row] = v0.y;
        As[0][a_col + 2][a_row] = v0.z; As[0][a_col + 3][a_row] = v0.w;
        As[0][a_col + 0][a_row + 64] = v1.x; As[0][a_col + 1][a_row + 64] = v1.y;
        As[0][a_col + 2][a_row + 64] = v1.z; As[0][a_col + 3][a_row + 64] = v1.w;

        if (BLAYOUT == BL_NT) {
            const float* pB = B + (size_t)(bn + a_row) * K + a_col;
            float4 w0 = *(const float4*)(pB);
            float4 w1 = *(const float4*)(pB + (size_t)64 * K);
            Bs[0][a_col + 0][a_row] = w0.x; Bs[0][a_col + 1][a_row] = w0.y;
            Bs[0][a_col + 2][a_row] = w0.z; Bs[0][a_col + 3][a_row] = w0.w;
            Bs[0][a_col + 0][a_row + 64] = w1.x; Bs[0][a_col + 1][a_row + 64] = w1.y;
            Bs[0][a_col + 2][a_row + 64] = w1.z; Bs[0][a_col + 3][a_row + 64] = w1.w;
        } else {
            const float* pB = B + (size_t)bnn_row * N + bn + bnn_col;
            float4 w0 = *(const float4*)(pB);
            float4 w1 = *(const float4*)(pB + (size_t)8 * N);
            *(float4*)&Bs[0][bnn_row][bnn_col] = w0;
            *(float4*)&Bs[0][bnn_row + 8][bnn_col] = w1;
        }
    }
    __syncthreads();

    for (int kt = 0; kt < ntiles; kt++) {
        const int cur = kt & 1;
        const bool has_next = (kt + 1) < ntiles;
        float4 na0, na1, nb0, nb1;
        if (has_next) {
            const int k0 = (kt + 1) * BK;
            const float* p = pA + k0;
            na0 = *(const float4*)(p);
            na1 = *(const float4*)(p + (size_t)64 * K);
            if (BLAYOUT == BL_NT) {
                const float* pB = B + (size_t)(bn + a_row) * K + k0 + a_col;
                nb0 = *(const float4*)(pB);
                nb1 = *(const float4*)(pB + (size_t)64 * K);
            } else {
                const float* pB = B + (size_t)(k0 + bnn_row) * N + bn + bnn_col;
                nb0 = *(const float4*)(pB);
                nb1 = *(const float4*)(pB + (size_t)8 * N);
            }
        }

        // compute on current buffer
#pragma unroll
        for (int k = 0; k < BK; k++) {
            float aF[TM], bF[TN];
            *(float4*)&aF[0] = *(const float4*)&As[cur][k][tr];
            *(float4*)&aF[4] = *(const float4*)&As[cur][k][tr + 4];
            *(float4*)&bF[0] = *(const float4*)&Bs[cur][k][tc];
            *(float4*)&bF[4] = *(const float4*)&Bs[cur][k][tc + 4];
#pragma unroll
            for (int i = 0; i < TM; i++)
#pragma unroll
                for (int j = 0; j < TN; j++)
                    acc[i][j] += aF[i] * bF[j];
        }

        if (has_next) {
            const int nxt = cur ^ 1;
            As[nxt][a_col + 0][a_row] = na0.x; As[nxt][a_col + 1][a_row] = na0.y;
            As[nxt][a_col + 2][a_row] = na0.z; As[nxt][a_col + 3][a_row] = na0.w;
            As[nxt][a_col + 0][a_row + 64] = na1.x; As[nxt][a_col + 1][a_row + 64] = na1.y;
            As[nxt][a_col + 2][a_row + 64] = na1.z; As[nxt][a_col + 3][a_row + 64] = na1.w;
            if (BLAYOUT == BL_NT) {
                Bs[nxt][a_col + 0][a_row] = nb0.x; Bs[nxt][a_col + 1][a_row] = nb0.y;
                Bs[nxt][a_col + 2][a_row] = nb0.z; Bs[nxt][a_col + 3][a_row] = nb0.w;
                Bs[nxt][a_col + 0][a_row + 64] = nb1.x; Bs[nxt][a_col + 1][a_row + 64] = nb1.y;
                Bs[nxt][a_col + 2][a_row + 64] = nb1.z; Bs[nxt][a_col + 3][a_row + 64] = nb1.w;
            } else {
                *(float4*)&Bs[nxt][bnn_row][bnn_col] = nb0;
                *(float4*)&Bs[nxt][bnn_row + 8][bnn_col] = nb1;
            }
        }
        __syncthreads();
    }

    // ---------------- epilogue ----------------
#pragma unroll
    for (int i = 0; i < TM; i++) {
        const int m = bm + tr + i;
        const size_t rowoff = (size_t)m * N + bn + tc;
#pragma unroll
        for (int j = 0; j < TN; j++) {
            const float a = acc[i][j];
            float v;
            if (EPI == EPI_FWD) {
                v = tanhf(a + X[bn + tc + j]);
            } else if (EPI == EPI_ERR) {
                v = X[rowoff + j] - tanhf(a);
            } else if (EPI == EPI_UPD) {
                v = C[rowoff + j] + LRATE * (a - X[rowoff + j]);
            } else { // EPI_UPD3: err == state
                v = C[rowoff + j] * (1.0f - LRATE) + LRATE * a;
            }
            C[rowoff + j] = v;
        }
    }
}

// ---------------- helpers ----------------
__global__ void copy_kernel(float* __restrict__ dst, const float* __restrict__ src, int n) {
    for (int i = blockIdx.x * blockDim.x + threadIdx.x; i < n; i += gridDim.x * blockDim.x)
        dst[i] = src[i];
}

__global__ void zero1_kernel(float* p) { *p = 0.0f; }

__global__ void sumsq_kernel(const float* __restrict__ a, int n, float* out) {
    float s = 0.0f;
    for (int i = blockIdx.x * blockDim.x + threadIdx.x; i < n; i += gridDim.x * blockDim.x) {
        float v = a[i];
        s += v * v;
    }
#pragma unroll
    for (int o = 16; o > 0; o >>= 1) s += __shfl_xor_sync(0xFFFFFFFFu, s, o);
    __shared__ float ws[32];
    if ((threadIdx.x & 31) == 0) ws[threadIdx.x >> 5] = s;
    __syncthreads();
    if (threadIdx.x < 32) {
        s = (threadIdx.x < (blockDim.x >> 5)) ? ws[threadIdx.x] : 0.0f;
#pragma unroll
        for (int o = 16; o > 0; o >>= 1) s += __shfl_xor_sync(0xFFFFFFFFu, s, o);
        if (threadIdx.x == 0) atomicAdd(out, 0.5f * s);
    }
}

// ---------------- launcher ----------------
extern "C" void kernel_launch(void* const* d_in, const int* in_sizes, int n_in,
                              void* d_out, int out_size)
{
    const float* x  = (const float*)d_in[0];
    const float* W0 = (const float*)d_in[1];
    const float* b0 = (const float*)d_in[2];
    const float* W1 = (const float*)d_in[3];
    const float* b1 = (const float*)d_in[4];
    const float* W2 = (const float*)d_in[5];
    const float* b2 = (const float*)d_in[6];

    float *r1, *r2, *r3, *e0, *e1, *e2;
    cudaGetSymbolAddress((void**)&r1, g_r1);
    cudaGetSymbolAddress((void**)&r2, g_r2);
    cudaGetSymbolAddress((void**)&r3, g_r3);
    cudaGetSymbolAddress((void**)&e0, g_e0);
    cudaGetSymbolAddress((void**)&e1, g_e1);
    cudaGetSymbolAddress((void**)&e2, g_e2);

    const dim3 blk(256);
    const dim3 gr_d1(D1 / BN, BATCH / BM);
    const dim3 gr_d2(D2 / BN, BATCH / BM);
    const dim3 gr_d3(D3 / BN, BATCH / BM);
    const dim3 gr_d0(D0 / BN, BATCH / BM);

    // ---- forward init: r[i+1] = tanh(r[i] @ W_i^T + b_i) ----
    gemm_epi<BL_NT, EPI_FWD><<<gr_d1, blk>>>(x,  W0, b0, r1, BATCH, D1, D0);
    gemm_epi<BL_NT, EPI_FWD><<<gr_d2, blk>>>(r1, W1, b1, r2, BATCH, D2, D1);
    gemm_epi<BL_NT, EPI_FWD><<<gr_d3, blk>>>(r2, W2, b2, r3, BATCH, D3, D2);

    // ---- relaxation steps ----
    for (int s = 0; s < NSTEPS; s++) {
        // errors: e[i] = r[i] - tanh(r[i+1] @ W_i)
        gemm_epi<BL_NN, EPI_ERR><<<gr_d2, blk>>>(r3, W2, r2, e2, BATCH, D2, D3);
        gemm_epi<BL_NN, EPI_ERR><<<gr_d1, blk>>>(r2, W1, r1, e1, BATCH, D1, D2);
        gemm_epi<BL_NN, EPI_ERR><<<gr_d0, blk>>>(r1, W0, x,  e0, BATCH, D0, D1);
        // updates: r[i] += LR*(-e[i] + e[i-1] @ W_{i-1}^T)
        gemm_epi<BL_NT, EPI_UPD><<<gr_d1, blk>>>(e0, W0, e1, r1, BATCH, D1, D0);
        gemm_epi<BL_NT, EPI_UPD><<<gr_d2, blk>>>(e1, W1, e2, r2, BATCH, D2, D1);
        gemm_epi<BL_NT, EPI_UPD3><<<gr_d3, blk>>>(e2, W2, r3, r3, BATCH, D3, D2);
    }

    // ---- final errors for energy ----
    gemm_epi<BL_NN, EPI_ERR><<<gr_d2, blk>>>(r3, W2, r2, e2, BATCH, D2, D3);
    gemm_epi<BL_NN, EPI_ERR><<<gr_d1, blk>>>(r2, W1, r1, e1, BATCH, D1, D2);
    gemm_epi<BL_NN, EPI_ERR><<<gr_d0, blk>>>(r1, W0, x,  e0, BATCH, D0, D1);

    // ---- outputs: r3 flattened, then scalar total_error ----
    float* out = (float*)d_out;
    const int n_r3 = BATCH * D3;
    int ncopy = out_size < n_r3 ? out_size : n_r3;
    copy_kernel<<<2048, 256>>>(out, r3, ncopy);

    if (out_size > n_r3) {
        float* esc = out + n_r3;
        zero1_kernel<<<1, 1>>>(esc);
        sumsq_kernel<<<296, 256>>>(e0, BATCH * D0, esc);
        sumsq_kernel<<<296, 256>>>(e1, BATCH * D1, esc);
        sumsq_kernel<<<296, 256>>>(e2, BATCH * D2, esc);
        sumsq_kernel<<<296, 256>>>(r3, BATCH * D3, esc);
    }
}

// round 5
// speedup vs baseline: 2.2251x; 2.2251x over previous
#include <cuda_runtime.h>
#include <cstdint>

#define BATCH 4096
#define D0 1024
#define D1 2048
#define D2 2048
#define D3 512
#define NSTEPS 20
#define LRATE 0.1f

// ---------------- device scratch (allocation-free rule: __device__ globals) ----
__device__ __align__(128) float g_r1[BATCH * D1];
__device__ __align__(128) float g_r2[BATCH * D2];
__device__ __align__(128) float g_r3[BATCH * D3];
__device__ __align__(128) float g_e0[BATCH * D0];
__device__ __align__(128) float g_e1[BATCH * D1];
__device__ __align__(128) float g_e2[BATCH * D2];
// tf32-rounded twins (GEMM operands only)
__device__ __align__(128) float g_r1r[BATCH * D1];
__device__ __align__(128) float g_r2r[BATCH * D2];
__device__ __align__(128) float g_r3r[BATCH * D3];
__device__ __align__(128) float g_e0r[BATCH * D0];
__device__ __align__(128) float g_e1r[BATCH * D1];
__device__ __align__(128) float g_e2r[BATCH * D2];
__device__ __align__(128) float g_xr[BATCH * D0];
__device__ __align__(128) float g_W0r[D1 * D0];
__device__ __align__(128) float g_W1r[D2 * D1];
__device__ __align__(128) float g_W2r[D3 * D2];

// ---------------- helpers ----------------
__device__ __forceinline__ float rnd_tf32(float x) {
    float y;
    asm("cvt.rna.tf32.f32 %0, %1;" : "=f"(y) : "f"(x));
    return y;
}

__device__ __forceinline__ void mma_tf32(float* c, const uint32_t* a, const uint32_t* b) {
    asm volatile(
        "mma.sync.aligned.m16n8k8.row.col.f32.tf32.tf32.f32 "
        "{%0,%1,%2,%3}, {%4,%5,%6,%7}, {%8,%9}, {%0,%1,%2,%3};"
        : "+f"(c[0]), "+f"(c[1]), "+f"(c[2]), "+f"(c[3])
        : "r"(a[0]), "r"(a[1]), "r"(a[2]), "r"(a[3]), "r"(b[0]), "r"(b[1]));
}

// ---------------- GEMM config ----------------
constexpr int BM = 128, BN = 128, BK = 16;
constexpr int PAD = 4;

enum { BL_NT = 0, BL_NN = 1 };      // B layout: NT => B is (N,K) row-major; NN => B is (K,N) row-major
enum { EPI_FWD = 0,                 // C = tanh(acc + X[n])            (X = bias, len N)
       EPI_ERR = 1,                 // C = X[m,n] - tanh(acc)          (X = target matrix)
       EPI_UPD = 2,                 // C += LR*(acc - X[m,n])          (X = error matrix, X != C)
       EPI_UPD3 = 3 };              // C = C*(1-LR) + LR*acc           (last layer: err == state)

// C(M,N) = A(M,K) @ op(B); A,B pre-rounded to tf32. Writes full C and rounded Cr.
template <int BLAYOUT, int EPI>
__global__ __launch_bounds__(256, 2)
void gemm_epi(const float* __restrict__ A, const float* __restrict__ B,
              const float* __restrict__ X, float* __restrict__ C,
              float* __restrict__ Cr, int M, int N, int K)
{
    __shared__ __align__(16) float As[2][BK][BM + PAD];
    __shared__ __align__(16) float Bs[2][BK][BN + PAD];

    const int tid = threadIdx.x;
    const int wid = tid >> 5;
    const int lane = tid & 31;
    const int gr = lane >> 2;   // 0..7
    const int ct = lane & 3;    // 0..3
    const int wm = (wid & 3) * 32;   // warp row offset in tile (4 warps down)
    const int wn = (wid >> 2) * 64;  // warp col offset in tile (2 warps across)

    const int bm = blockIdx.y * BM;
    const int bn = blockIdx.x * BN;

    // loader indices (identical to R1 kernel)
    const int a_row = tid >> 2;          // 0..63
    const int a_col = (tid & 3) * 4;     // 0,4,8,12
    const int bnn_row = tid >> 5;        // 0..7
    const int bnn_col = (tid & 31) * 4;  // 0..124

    float acc[2][8][4];
#pragma unroll
    for (int mi = 0; mi < 2; mi++)
#pragma unroll
        for (int j = 0; j < 8; j++)
#pragma unroll
            for (int q = 0; q < 4; q++) acc[mi][j][q] = 0.0f;

    const int ntiles = K / BK;
    const float* pA = A + (size_t)(bm + a_row) * K + a_col;

    // --- preload tile 0 ---
    {
        float4 v0 = *(const float4*)(pA);
        float4 v1 = *(const float4*)(pA + (size_t)64 * K);
        As[0][a_col + 0][a_row] = v0.x; As[0][a_col + 1][a_row] = v0.y;
        As[0][a_col + 2][a_row] = v0.z; As[0][a_col + 3][a_row] = v0.w;
        As[0][a_col + 0][a_row + 64] = v1.x; As[0][a_col + 1][a_row + 64] = v1.y;
        As[0][a_col + 2][a_row + 64] = v1.z; As[0][a_col + 3][a_row + 64] = v1.w;

        if (BLAYOUT == BL_NT) {
            const float* pB = B + (size_t)(bn + a_row) * K + a_col;
            float4 w0 = *(const float4*)(pB);
            float4 w1 = *(const float4*)(pB + (size_t)64 * K);
            Bs[0][a_col + 0][a_row] = w0.x; Bs[0][a_col + 1][a_row] = w0.y;
            Bs[0][a_col + 2][a_row] = w0.z; Bs[0][a_col + 3][a_row] = w0.w;
            Bs[0][a_col + 0][a_row + 64] = w1.x; Bs[0][a_col + 1][a_row + 64] = w1.y;
            Bs[0][a_col + 2][a_row + 64] = w1.z; Bs[0][a_col + 3][a_row + 64] = w1.w;
        } else {
            const float* pB = B + (size_t)bnn_row * N + bn + bnn_col;
            float4 w0 = *(const float4*)(pB);
            float4 w1 = *(const float4*)(pB + (size_t)8 * N);
            *(float4*)&Bs[0][bnn_row][bnn_col] = w0;
            *(float4*)&Bs[0][bnn_row + 8][bnn_col] = w1;
        }
    }
    __syncthreads();

    for (int kt = 0; kt < ntiles; kt++) {
        const int cur = kt & 1;
        const bool has_next = (kt + 1) < ntiles;
        float4 na0, na1, nb0, nb1;
        if (has_next) {
            const int k0 = (kt + 1) * BK;
            const float* p = pA + k0;
            na0 = *(const float4*)(p);
            na1 = *(const float4*)(p + (size_t)64 * K);
            if (BLAYOUT == BL_NT) {
                const float* pB = B + (size_t)(bn + a_row) * K + k0 + a_col;
                nb0 = *(const float4*)(pB);
                nb1 = *(const float4*)(pB + (size_t)64 * K);
            } else {
                const float* pB = B + (size_t)(k0 + bnn_row) * N + bn + bnn_col;
                nb0 = *(const float4*)(pB);
                nb1 = *(const float4*)(pB + (size_t)8 * N);
            }
        }

        // ---- tensor-core compute on current buffer: two k8 steps ----
#pragma unroll
        for (int k8 = 0; k8 < 2; k8++) {
            const int kb = k8 * 8;
            uint32_t afr[2][4];
            uint32_t bfr[8][2];
#pragma unroll
            for (int mi = 0; mi < 2; mi++) {
                const int m = wm + mi * 16;
                afr[mi][0] = __float_as_uint(As[cur][kb + ct][m + gr]);
                afr[mi][1] = __float_as_uint(As[cur][kb + ct][m + gr + 8]);
                afr[mi][2] = __float_as_uint(As[cur][kb + ct + 4][m + gr]);
                afr[mi][3] = __float_as_uint(As[cur][kb + ct + 4][m + gr + 8]);
            }
#pragma unroll
            for (int j = 0; j < 8; j++) {
                const int n = wn + j * 8;
                bfr[j][0] = __float_as_uint(Bs[cur][kb + ct][n + gr]);
                bfr[j][1] = __float_as_uint(Bs[cur][kb + ct + 4][n + gr]);
            }
#pragma unroll
            for (int mi = 0; mi < 2; mi++)
#pragma unroll
                for (int j = 0; j < 8; j++)
                    mma_tf32(acc[mi][j], afr[mi], bfr[j]);
        }

        if (has_next) {
            const int nxt = cur ^ 1;
            As[nxt][a_col + 0][a_row] = na0.x; As[nxt][a_col + 1][a_row] = na0.y;
            As[nxt][a_col + 2][a_row] = na0.z; As[nxt][a_col + 3][a_row] = na0.w;
            As[nxt][a_col + 0][a_row + 64] = na1.x; As[nxt][a_col + 1][a_row + 64] = na1.y;
            As[nxt][a_col + 2][a_row + 64] = na1.z; As[nxt][a_col + 3][a_row + 64] = na1.w;
            if (BLAYOUT == BL_NT) {
                Bs[nxt][a_col + 0][a_row] = nb0.x; Bs[nxt][a_col + 1][a_row] = nb0.y;
                Bs[nxt][a_col + 2][a_row] = nb0.z; Bs[nxt][a_col + 3][a_row] = nb0.w;
                Bs[nxt][a_col + 0][a_row + 64] = nb1.x; Bs[nxt][a_col + 1][a_row + 64] = nb1.y;
                Bs[nxt][a_col + 2][a_row + 64] = nb1.z; Bs[nxt][a_col + 3][a_row + 64] = nb1.w;
            } else {
                *(float4*)&Bs[nxt][bnn_row][bnn_col] = nb0;
                *(float4*)&Bs[nxt][bnn_row + 8][bnn_col] = nb1;
            }
        }
        __syncthreads();
    }

    // ---------------- epilogue ----------------
#pragma unroll
    for (int mi = 0; mi < 2; mi++) {
#pragma unroll
        for (int half = 0; half < 2; half++) {
            const int m = bm + wm + mi * 16 + gr + half * 8;
#pragma unroll
            for (int j = 0; j < 8; j++) {
                const int n = bn + wn + j * 8 + 2 * ct;
                const size_t off = (size_t)m * N + n;
                const float a0 = acc[mi][j][2 * half + 0];
                const float a1 = acc[mi][j][2 * half + 1];
                float v0, v1;
                if (EPI == EPI_FWD) {
                    v0 = tanhf(a0 + X[n]);
                    v1 = tanhf(a1 + X[n + 1]);
                } else if (EPI == EPI_ERR) {
                    const float2 xv = *(const float2*)(X + off);
                    v0 = xv.x - tanhf(a0);
                    v1 = xv.y - tanhf(a1);
                } else if (EPI == EPI_UPD) {
                    const float2 cv = *(const float2*)(C + off);
                    const float2 xv = *(const float2*)(X + off);
                    v0 = cv.x + LRATE * (a0 - xv.x);
                    v1 = cv.y + LRATE * (a1 - xv.y);
                } else {  // EPI_UPD3
                    const float2 cv = *(const float2*)(C + off);
                    v0 = cv.x * (1.0f - LRATE) + LRATE * a0;
                    v1 = cv.y * (1.0f - LRATE) + LRATE * a1;
                }
                *(float2*)(C + off) = make_float2(v0, v1);
                *(float2*)(Cr + off) = make_float2(rnd_tf32(v0), rnd_tf32(v1));
            }
        }
    }
}

// ---------------- prep / output helpers ----------------
__global__ void round_copy(const float* __restrict__ in, float* __restrict__ out, int n) {
    for (int i = blockIdx.x * blockDim.x + threadIdx.x; i < n; i += gridDim.x * blockDim.x)
        out[i] = rnd_tf32(in[i]);
}

__global__ void copy_kernel(float* __restrict__ dst, const float* __restrict__ src, int n) {
    for (int i = blockIdx.x * blockDim.x + threadIdx.x; i < n; i += gridDim.x * blockDim.x)
        dst[i] = src[i];
}

__global__ void zero1_kernel(float* p) { *p = 0.0f; }

__global__ void sumsq_kernel(const float* __restrict__ a, int n, float* out) {
    float s = 0.0f;
    for (int i = blockIdx.x * blockDim.x + threadIdx.x; i < n; i += gridDim.x * blockDim.x) {
        float v = a[i];
        s += v * v;
    }
#pragma unroll
    for (int o = 16; o > 0; o >>= 1) s += __shfl_xor_sync(0xFFFFFFFFu, s, o);
    __shared__ float ws[32];
    if ((threadIdx.x & 31) == 0) ws[threadIdx.x >> 5] = s;
    __syncthreads();
    if (threadIdx.x < 32) {
        s = (threadIdx.x < (blockDim.x >> 5)) ? ws[threadIdx.x] : 0.0f;
#pragma unroll
        for (int o = 16; o > 0; o >>= 1) s += __shfl_xor_sync(0xFFFFFFFFu, s, o);
        if (threadIdx.x == 0) atomicAdd(out, 0.5f * s);
    }
}

// ---------------- launcher ----------------
extern "C" void kernel_launch(void* const* d_in, const int* in_sizes, int n_in,
                              void* d_out, int out_size)
{
    const float* x  = (const float*)d_in[0];
    const float* W0 = (const float*)d_in[1];
    const float* b0 = (const float*)d_in[2];
    const float* W1 = (const float*)d_in[3];
    const float* b1 = (const float*)d_in[4];
    const float* W2 = (const float*)d_in[5];
    const float* b2 = (const float*)d_in[6];

    float *r1, *r2, *r3, *e0, *e1, *e2;
    float *r1r, *r2r, *r3r, *e0r, *e1r, *e2r, *xr;
    float *W0r, *W1r, *W2r;
    cudaGetSymbolAddress((void**)&r1, g_r1);
    cudaGetSymbolAddress((void**)&r2, g_r2);
    cudaGetSymbolAddress((void**)&r3, g_r3);
    cudaGetSymbolAddress((void**)&e0, g_e0);
    cudaGetSymbolAddress((void**)&e1, g_e1);
    cudaGetSymbolAddress((void**)&e2, g_e2);
    cudaGetSymbolAddress((void**)&r1r, g_r1r);
    cudaGetSymbolAddress((void**)&r2r, g_r2r);
    cudaGetSymbolAddress((void**)&r3r, g_r3r);
    cudaGetSymbolAddress((void**)&e0r, g_e0r);
    cudaGetSymbolAddress((void**)&e1r, g_e1r);
    cudaGetSymbolAddress((void**)&e2r, g_e2r);
    cudaGetSymbolAddress((void**)&xr, g_xr);
    cudaGetSymbolAddress((void**)&W0r, g_W0r);
    cudaGetSymbolAddress((void**)&W1r, g_W1r);
    cudaGetSymbolAddress((void**)&W2r, g_W2r);

    // ---- prep: round operands to nearest-tf32 ----
    round_copy<<<512, 256>>>(x, xr, BATCH * D0);
    round_copy<<<512, 256>>>(W0, W0r, D1 * D0);
    round_copy<<<512, 256>>>(W1, W1r, D2 * D1);
    round_copy<<<512, 256>>>(W2, W2r, D3 * D2);

    const dim3 blk(256);
    const dim3 gr_d1(D1 / BN, BATCH / BM);
    const dim3 gr_d2(D2 / BN, BATCH / BM);
    const dim3 gr_d3(D3 / BN, BATCH / BM);
    const dim3 gr_d0(D0 / BN, BATCH / BM);

    // ---- forward init: r[i+1] = tanh(r[i] @ W_i^T + b_i) ----
    gemm_epi<BL_NT, EPI_FWD><<<gr_d1, blk>>>(xr,  W0r, b0, r1, r1r, BATCH, D1, D0);
    gemm_epi<BL_NT, EPI_FWD><<<gr_d2, blk>>>(r1r, W1r, b1, r2, r2r, BATCH, D2, D1);
    gemm_epi<BL_NT, EPI_FWD><<<gr_d3, blk>>>(r2r, W2r, b2, r3, r3r, BATCH, D3, D2);

    // ---- relaxation steps ----
    for (int s = 0; s < NSTEPS; s++) {
        // errors: e[i] = r[i] - tanh(r[i+1] @ W_i)
        gemm_epi<BL_NN, EPI_ERR><<<gr_d2, blk>>>(r3r, W2r, r2, e2, e2r, BATCH, D2, D3);
        gemm_epi<BL_NN, EPI_ERR><<<gr_d1, blk>>>(r2r, W1r, r1, e1, e1r, BATCH, D1, D2);
        gemm_epi<BL_NN, EPI_ERR><<<gr_d0, blk>>>(r1r, W0r, x,  e0, e0r, BATCH, D0, D1);
        // updates: r[i] += LR*(-e[i] + e[i-1] @ W_{i-1}^T)
        gemm_epi<BL_NT, EPI_UPD><<<gr_d1, blk>>>(e0r, W0r, e1, r1, r1r, BATCH, D1, D0);
        gemm_epi<BL_NT, EPI_UPD><<<gr_d2, blk>>>(e1r, W1r, e2, r2, r2r, BATCH, D2, D1);
        gemm_epi<BL_NT, EPI_UPD3><<<gr_d3, blk>>>(e2r, W2r, r3, r3, r3r, BATCH, D3, D2);
    }

    // ---- final errors for energy ----
    gemm_epi<BL_NN, EPI_ERR><<<gr_d2, blk>>>(r3r, W2r, r2, e2, e2r, BATCH, D2, D3);
    gemm_epi<BL_NN, EPI_ERR><<<gr_d1, blk>>>(r2r, W1r, r1, e1, e1r, BATCH, D1, D2);
    gemm_epi<BL_NN, EPI_ERR><<<gr_d0, blk>>>(r1r, W0r, x,  e0, e0r, BATCH, D0, D1);

    // ---- outputs: r3 flattened, then scalar total_error ----
    float* out = (float*)d_out;
    const int n_r3 = BATCH * D3;
    int ncopy = out_size < n_r3 ? out_size : n_r3;
    copy_kernel<<<2048, 256>>>(out, r3, ncopy);

    if (out_size > n_r3) {
        float* esc = out + n_r3;
        zero1_kernel<<<1, 1>>>(esc);
        sumsq_kernel<<<296, 256>>>(e0, BATCH * D0, esc);
        sumsq_kernel<<<296, 256>>>(e1, BATCH * D1, esc);
        sumsq_kernel<<<296, 256>>>(e2, BATCH * D2, esc);
        sumsq_kernel<<<296, 256>>>(r3, BATCH * D3, esc);
    }
}

// round 7
// speedup vs baseline: 3.0134x; 1.3542x over previous
#include <cuda_runtime.h>
#include <cstdint>

#define BATCH 4096
#define D0 1024
#define D1 2048
#define D2 2048
#define D3 512
#define NSTEPS 20
#define LRATE 0.1f

// ---------------- device scratch (allocation-free rule: __device__ globals) ----
__device__ __align__(128) float g_r1[BATCH * D1];
__device__ __align__(128) float g_r2[BATCH * D2];
__device__ __align__(128) float g_r3[BATCH * D3];
__device__ __align__(128) float g_e0[BATCH * D0];
__device__ __align__(128) float g_e1[BATCH * D1];
__device__ __align__(128) float g_e2[BATCH * D2];
// tf32-rounded twins (GEMM operands only)
__device__ __align__(128) float g_r1r[BATCH * D1];
__device__ __align__(128) float g_r2r[BATCH * D2];
__device__ __align__(128) float g_r3r[BATCH * D3];
__device__ __align__(128) float g_e0r[BATCH * D0];
__device__ __align__(128) float g_e1r[BATCH * D1];
__device__ __align__(128) float g_e2r[BATCH * D2];
__device__ __align__(128) float g_xr[BATCH * D0];
// rounded weights + rounded transposes (so every GEMM is NT, K-major B)
__device__ __align__(128) float g_W0r[D1 * D0];
__device__ __align__(128) float g_W1r[D2 * D1];
__device__ __align__(128) float g_W2r[D3 * D2];
__device__ __align__(128) float g_W0t[D0 * D1];
__device__ __align__(128) float g_W1t[D1 * D2];
__device__ __align__(128) float g_W2t[D2 * D3];

// ---------------- helpers ----------------
__device__ __forceinline__ float rnd_tf32(float x) {
    float y;
    asm("cvt.rna.tf32.f32 %0, %1;" : "=f"(y) : "f"(x));
    return y;
}

__device__ __forceinline__ void mma_tf32(float* c, const uint32_t* a, const uint32_t* b) {
    asm volatile(
        "mma.sync.aligned.m16n8k8.row.col.f32.tf32.tf32.f32 "
        "{%0,%1,%2,%3}, {%4,%5,%6,%7}, {%8,%9}, {%0,%1,%2,%3};"
        : "+f"(c[0]), "+f"(c[1]), "+f"(c[2]), "+f"(c[3])
        : "r"(a[0]), "r"(a[1]), "r"(a[2]), "r"(a[3]), "r"(b[0]), "r"(b[1]));
}

__device__ __forceinline__ void cp16(uint32_t s, const void* g) {
    asm volatile("cp.async.cg.shared.global [%0], [%1], 16;" :: "r"(s), "l"(g));
}

// swizzled float index for element (row, k) in a [128][32] tile
__device__ __forceinline__ int swidx(int row, int k) {
    return (row * 32 + k) ^ ((row & 7) << 2);
}

// ---------------- GEMM config ----------------
constexpr int BM = 128, BN = 128, BK = 32;
constexpr int STAGES = 3;
constexpr int STAGE_FLOATS = 2 * BM * BK;               // A tile + B tile = 8192 floats
constexpr int DSMEM = STAGES * STAGE_FLOATS * 4;        // 96 KB

enum { EPI_FWD = 0, EPI_ERR = 1, EPI_UPD = 2, EPI_UPD3 = 3 };

// fill one pipeline stage (A tile [BM][BK] + B tile [BN][BK], both K-major gmem)
__device__ __forceinline__ void fill_stage(uint32_t sbase, const float* __restrict__ A,
                                           const float* __restrict__ B, int K,
                                           int bm, int bn, int kt, int tid) {
    const float* Ag = A + (size_t)bm * K + (size_t)kt * BK;
    const float* Bg = B + (size_t)bn * K + (size_t)kt * BK;
#pragma unroll
    for (int i = 0; i < 4; i++) {
        const int c = tid + (i << 8);          // 0..1023 chunk id
        const int row = c >> 3;
        const int kc = (c & 7) << 2;           // k of chunk start
        const uint32_t d = sbase + ((uint32_t)swidx(row, kc) << 2);
        cp16(d, Ag + (size_t)row * K + kc);
    }
#pragma unroll
    for (int i = 0; i < 4; i++) {
        const int c = tid + (i << 8);
        const int row = c >> 3;
        const int kc = (c & 7) << 2;
        const uint32_t d = sbase + (uint32_t)(BM * BK * 4) + ((uint32_t)swidx(row, kc) << 2);
        cp16(d, Bg + (size_t)row * K + kc);
    }
    asm volatile("cp.async.commit_group;" ::: "memory");
}

// C(M,N) = A(M,K) @ B(N,K)^T; A,B pre-rounded tf32. Writes full C and rounded Cr.
template <int EPI>
__global__ __launch_bounds__(256, 2)
void gemm_epi(const float* __restrict__ A, const float* __restrict__ B,
              const float* __restrict__ X, float* __restrict__ C,
              float* __restrict__ Cr, int N, int K)
{
    extern __shared__ float smem[];
    const uint32_t sb = (uint32_t)__cvta_generic_to_shared(smem);

    const int tid = threadIdx.x;
    const int wid = tid >> 5;
    const int lane = tid & 31;
    const int gr = lane >> 2;        // 0..7
    const int ct = lane & 3;         // 0..3
    const int wm = (wid & 3) * 32;   // 4 warps down
    const int wn = (wid >> 2) * 64;  // 2 warps across

    const int bm = blockIdx.y * BM;
    const int bn = blockIdx.x * BN;
    const int NT = K / BK;

    float acc[2][8][4];
#pragma unroll
    for (int mi = 0; mi < 2; mi++)
#pragma unroll
        for (int j = 0; j < 8; j++)
#pragma unroll
            for (int q = 0; q < 4; q++) acc[mi][j][q] = 0.0f;

    // prologue: stages 0,1
    fill_stage(sb + 0 * STAGE_FLOATS * 4, A, B, K, bm, bn, 0, tid);
    fill_stage(sb + 1 * STAGE_FLOATS * 4, A, B, K, bm, bn, 1, tid);

    int buf = 0;
    for (int kt = 0; kt < NT; kt++) {
        asm volatile("cp.async.wait_group 1;" ::: "memory");
        __syncthreads();

        const int nf = kt + 2;
        if (nf < NT) {
            int fb = buf + 2; if (fb >= STAGES) fb -= STAGES;
            fill_stage(sb + fb * STAGE_FLOATS * 4, A, B, K, bm, bn, nf, tid);
        }

        const float* As_ = smem + buf * STAGE_FLOATS;
        const float* Bs_ = As_ + BM * BK;

#pragma unroll
        for (int k8 = 0; k8 < 4; k8++) {
            const int kb = k8 * 8;
            uint32_t afr[2][4];
            uint32_t bfr[8][2];
#pragma unroll
            for (int mi = 0; mi < 2; mi++) {
                const int r0 = wm + mi * 16 + gr;
                afr[mi][0] = __float_as_uint(As_[swidx(r0,     kb + ct)]);
                afr[mi][1] = __float_as_uint(As_[swidx(r0 + 8, kb + ct)]);
                afr[mi][2] = __float_as_uint(As_[swidx(r0,     kb + ct + 4)]);
                afr[mi][3] = __float_as_uint(As_[swidx(r0 + 8, kb + ct + 4)]);
            }
#pragma unroll
            for (int j = 0; j < 8; j++) {
                const int n0 = wn + j * 8 + gr;
                bfr[j][0] = __float_as_uint(Bs_[swidx(n0, kb + ct)]);
                bfr[j][1] = __float_as_uint(Bs_[swidx(n0, kb + ct + 4)]);
            }
#pragma unroll
            for (int mi = 0; mi < 2; mi++)
#pragma unroll
                for (int j = 0; j < 8; j++)
                    mma_tf32(acc[mi][j], afr[mi], bfr[j]);
        }

        buf++; if (buf >= STAGES) buf = 0;
    }

    // ---------------- epilogue (same as R5, proven) ----------------
#pragma unroll
    for (int mi = 0; mi < 2; mi++) {
#pragma unroll
        for (int half = 0; half < 2; half++) {
            const int m = bm + wm + mi * 16 + gr + half * 8;
#pragma unroll
            for (int j = 0; j < 8; j++) {
                const int n = bn + wn + j * 8 + 2 * ct;
                const size_t off = (size_t)m * N + n;
                const float a0 = acc[mi][j][2 * half + 0];
                const float a1 = acc[mi][j][2 * half + 1];
                float v0, v1;
                if (EPI == EPI_FWD) {
                    v0 = tanhf(a0 + X[n]);
                    v1 = tanhf(a1 + X[n + 1]);
                } else if (EPI == EPI_ERR) {
                    const float2 xv = *(const float2*)(X + off);
                    v0 = xv.x - tanhf(a0);
                    v1 = xv.y - tanhf(a1);
                } else if (EPI == EPI_UPD) {
                    const float2 cv = *(const float2*)(C + off);
                    const float2 xv = *(const float2*)(X + off);
                    v0 = cv.x + LRATE * (a0 - xv.x);
                    v1 = cv.y + LRATE * (a1 - xv.y);
                } else {  // EPI_UPD3
                    const float2 cv = *(const float2*)(C + off);
                    v0 = cv.x * (1.0f - LRATE) + LRATE * a0;
                    v1 = cv.y * (1.0f - LRATE) + LRATE * a1;
                }
                *(float2*)(C + off) = make_float2(v0, v1);
                *(float2*)(Cr + off) = make_float2(rnd_tf32(v0), rnd_tf32(v1));
            }
        }
    }
}

// ---------------- prep / output helpers ----------------
__global__ void round_copy(const float* __restrict__ in, float* __restrict__ out, int n) {
    for (int i = blockIdx.x * blockDim.x + threadIdx.x; i < n; i += gridDim.x * blockDim.x)
        out[i] = rnd_tf32(in[i]);
}

// W (Nn,Kk) -> Wr (Nn,Kk) rounded, Wt (Kk,Nn) rounded-transpose
__global__ void trans_round(const float* __restrict__ W, float* __restrict__ Wr,
                            float* __restrict__ Wt, int Nn, int Kk) {
    __shared__ float t[32][33];
    const int k0 = blockIdx.x * 32;
    const int n0 = blockIdx.y * 32;
    const int tx = threadIdx.x;
    const int ty = threadIdx.y;  // 32x8
#pragma unroll
    for (int i = 0; i < 4; i++) {
        const int n = n0 + ty + i * 8;
        const float v = rnd_tf32(W[(size_t)n * Kk + k0 + tx]);
        Wr[(size_t)n * Kk + k0 + tx] = v;
        t[ty + i * 8][tx] = v;
    }
    __syncthreads();
#pragma unroll
    for (int i = 0; i < 4; i++) {
        const int k = k0 + ty + i * 8;
        Wt[(size_t)k * Nn + n0 + tx] = t[tx][ty + i * 8];
    }
}

__global__ void copy_kernel(float* __restrict__ dst, const float* __restrict__ src, int n) {
    for (int i = blockIdx.x * blockDim.x + threadIdx.x; i < n; i += gridDim.x * blockDim.x)
        dst[i] = src[i];
}

__global__ void zero1_kernel(float* p) { *p = 0.0f; }

__global__ void sumsq_kernel(const float* __restrict__ a, int n, float* out) {
    float s = 0.0f;
    for (int i = blockIdx.x * blockDim.x + threadIdx.x; i < n; i += gridDim.x * blockDim.x) {
        float v = a[i];
        s += v * v;
    }
#pragma unroll
    for (int o = 16; o > 0; o >>= 1) s += __shfl_xor_sync(0xFFFFFFFFu, s, o);
    __shared__ float ws[32];
    if ((threadIdx.x & 31) == 0) ws[threadIdx.x >> 5] = s;
    __syncthreads();
    if (threadIdx.x < 32) {
        s = (threadIdx.x < (blockDim.x >> 5)) ? ws[threadIdx.x] : 0.0f;
#pragma unroll
        for (int o = 16; o > 0; o >>= 1) s += __shfl_xor_sync(0xFFFFFFFFu, s, o);
        if (threadIdx.x == 0) atomicAdd(out, 0.5f * s);
    }
}

// ---------------- launcher ----------------
extern "C" void kernel_launch(void* const* d_in, const int* in_sizes, int n_in,
                              void* d_out, int out_size)
{
    const float* x  = (const float*)d_in[0];
    const float* W0 = (const float*)d_in[1];
    const float* b0 = (const float*)d_in[2];
    const float* W1 = (const float*)d_in[3];
    const float* b1 = (const float*)d_in[4];
    const float* W2 = (const float*)d_in[5];
    const float* b2 = (const float*)d_in[6];

    float *r1, *r2, *r3, *e0, *e1, *e2;
    float *r1r, *r2r, *r3r, *e0r, *e1r, *e2r, *xr;
    float *W0r, *W1r, *W2r, *W0t, *W1t, *W2t;
    cudaGetSymbolAddress((void**)&r1, g_r1);
    cudaGetSymbolAddress((void**)&r2, g_r2);
    cudaGetSymbolAddress((void**)&r3, g_r3);
    cudaGetSymbolAddress((void**)&e0, g_e0);
    cudaGetSymbolAddress((void**)&e1, g_e1);
    cudaGetSymbolAddress((void**)&e2, g_e2);
    cudaGetSymbolAddress((void**)&r1r, g_r1r);
    cudaGetSymbolAddress((void**)&r2r, g_r2r);
    cudaGetSymbolAddress((void**)&r3r, g_r3r);
    cudaGetSymbolAddress((void**)&e0r, g_e0r);
    cudaGetSymbolAddress((void**)&e1r, g_e1r);
    cudaGetSymbolAddress((void**)&e2r, g_e2r);
    cudaGetSymbolAddress((void**)&xr, g_xr);
    cudaGetSymbolAddress((void**)&W0r, g_W0r);
    cudaGetSymbolAddress((void**)&W1r, g_W1r);
    cudaGetSymbolAddress((void**)&W2r, g_W2r);
    cudaGetSymbolAddress((void**)&W0t, g_W0t);
    cudaGetSymbolAddress((void**)&W1t, g_W1t);
    cudaGetSymbolAddress((void**)&W2t, g_W2t);

    cudaFuncSetAttribute(gemm_epi<0>, cudaFuncAttributeMaxDynamicSharedMemorySize, DSMEM);
    cudaFuncSetAttribute(gemm_epi<1>, cudaFuncAttributeMaxDynamicSharedMemorySize, DSMEM);
    cudaFuncSetAttribute(gemm_epi<2>, cudaFuncAttributeMaxDynamicSharedMemorySize, DSMEM);
    cudaFuncSetAttribute(gemm_epi<3>, cudaFuncAttributeMaxDynamicSharedMemorySize, DSMEM);

    // ---- prep: round operands to nearest-tf32; transpose weights ----
    round_copy<<<512, 256>>>(x, xr, BATCH * D0);
    {
        dim3 b(32, 8);
        trans_round<<<dim3(D0 / 32, D1 / 32), b>>>(W0, W0r, W0t, D1, D0);
        trans_round<<<dim3(D1 / 32, D2 / 32), b>>>(W1, W1r, W1t, D2, D1);
        trans_round<<<dim3(D2 / 32, D3 / 32), b>>>(W2, W2r, W2t, D3, D2);
    }

    const dim3 blk(256);
    const dim3 gD1(D1 / BN, BATCH / BM);
    const dim3 gD2(D2 / BN, BATCH / BM);
    const dim3 gD3(D3 / BN, BATCH / BM);
    const dim3 gD0(D0 / BN, BATCH / BM);

    // ---- forward init: r[i+1] = tanh(r[i] @ W_i^T + b_i) ----
    gemm_epi<EPI_FWD><<<gD1, blk, DSMEM>>>(xr,  W0r, b0, r1, r1r, D1, D0);
    gemm_epi<EPI_FWD><<<gD2, blk, DSMEM>>>(r1r, W1r, b1, r2, r2r, D2, D1);
    gemm_epi<EPI_FWD><<<gD3, blk, DSMEM>>>(r2r, W2r, b2, r3, r3r, D3, D2);

    // ---- relaxation steps ----
    for (int s = 0; s < NSTEPS; s++) {
        // errors: e[i] = r[i] - tanh(r[i+1] @ W_i)   (NT with Wt)
        gemm_epi<EPI_ERR><<<gD2, blk, DSMEM>>>(r3r, W2t, r2, e2, e2r, D2, D3);
        gemm_epi<EPI_ERR><<<gD1, blk, DSMEM>>>(r2r, W1t, r1, e1, e1r, D1, D2);
        gemm_epi<EPI_ERR><<<gD0, blk, DSMEM>>>(r1r, W0t, x,  e0, e0r, D0, D1);
        // updates: r[i] += LR*(-e[i] + e[i-1] @ W_{i-1}^T)  (NT with Wr)
        gemm_epi<EPI_UPD><<<gD1, blk, DSMEM>>>(e0r, W0r, e1, r1, r1r, D1, D0);
        gemm_epi<EPI_UPD><<<gD2, blk, DSMEM>>>(e1r, W1r, e2, r2, r2r, D2, D1);
        gemm_epi<EPI_UPD3><<<gD3, blk, DSMEM>>>(e2r, W2r, r3, r3, r3r, D3, D2);
    }

    // ---- final errors for energy ----
    gemm_epi<EPI_ERR><<<gD2, blk, DSMEM>>>(r3r, W2t, r2, e2, e2r, D2, D3);
    gemm_epi<EPI_ERR><<<gD1, blk, DSMEM>>>(r2r, W1t, r1, e1, e1r, D1, D2);
    gemm_epi<EPI_ERR><<<gD0, blk, DSMEM>>>(r1r, W0t, x,  e0, e0r, D0, D1);

    // ---- outputs: r3 flattened, then scalar total_error ----
    float* out = (float*)d_out;
    const int n_r3 = BATCH * D3;
    int ncopy = out_size < n_r3 ? out_size : n_r3;
    copy_kernel<<<2048, 256>>>(out, r3, ncopy);

    if (out_size > n_r3) {
        float* esc = out + n_r3;
        zero1_kernel<<<1, 1>>>(esc);
        sumsq_kernel<<<296, 256>>>(e0, BATCH * D0, esc);
        sumsq_kernel<<<296, 256>>>(e1, BATCH * D1, esc);
        sumsq_kernel<<<296, 256>>>(e2, BATCH * D2, esc);
        sumsq_kernel<<<296, 256>>>(r3, BATCH * D3, esc);
    }
}

// round 8
// speedup vs baseline: 3.7513x; 1.2449x over previous
#include <cuda_runtime.h>
#include <cstdint>

#define BATCH 4096
#define D0 1024
#define D1 2048
#define D2 2048
#define D3 512
#define NSTEPS 20
#define LRATE 0.1f

// ---------------- device scratch (allocation-free rule: __device__ globals) ----
__device__ __align__(128) float g_r1[BATCH * D1];
__device__ __align__(128) float g_r2[BATCH * D2];
__device__ __align__(128) float g_r3[BATCH * D3];
__device__ __align__(128) float g_e0[BATCH * D0];
__device__ __align__(128) float g_e1[BATCH * D1];
__device__ __align__(128) float g_e2[BATCH * D2];
// tf32-rounded twins (GEMM operands only)
__device__ __align__(128) float g_r1r[BATCH * D1];
__device__ __align__(128) float g_r2r[BATCH * D2];
__device__ __align__(128) float g_r3r[BATCH * D3];
__device__ __align__(128) float g_e0r[BATCH * D0];
__device__ __align__(128) float g_e1r[BATCH * D1];
__device__ __align__(128) float g_e2r[BATCH * D2];
__device__ __align__(128) float g_xr[BATCH * D0];
// rounded weights + rounded transposes (so every GEMM is NT, K-major B)
__device__ __align__(128) float g_W0r[D1 * D0];
__device__ __align__(128) float g_W1r[D2 * D1];
__device__ __align__(128) float g_W2r[D3 * D2];
__device__ __align__(128) float g_W0t[D0 * D1];
__device__ __align__(128) float g_W1t[D1 * D2];
__device__ __align__(128) float g_W2t[D2 * D3];

// ---------------- helpers ----------------
__device__ __forceinline__ float rnd_tf32(float x) {
    float y;
    asm("cvt.rna.tf32.f32 %0, %1;" : "=f"(y) : "f"(x));
    return y;
}

__device__ __forceinline__ void mma_tf32(float* c, const uint32_t* a, const uint32_t* b) {
    asm volatile(
        "mma.sync.aligned.m16n8k8.row.col.f32.tf32.tf32.f32 "
        "{%0,%1,%2,%3}, {%4,%5,%6,%7}, {%8,%9}, {%0,%1,%2,%3};"
        : "+f"(c[0]), "+f"(c[1]), "+f"(c[2]), "+f"(c[3])
        : "r"(a[0]), "r"(a[1]), "r"(a[2]), "r"(a[3]), "r"(b[0]), "r"(b[1]));
}

__device__ __forceinline__ void cp16(uint32_t s, const void* g) {
    asm volatile("cp.async.cg.shared.global [%0], [%1], 16;" :: "r"(s), "l"(g));
}

// swizzled float index for element (row, k) in a [128][32] tile
__device__ __forceinline__ int swidx(int row, int k) {
    return (row * 32 + k) ^ ((row & 7) << 2);
}

// ---------------- GEMM config ----------------
constexpr int BM = 128, BN = 128, BK = 32;
constexpr int STAGES = 3;
constexpr int STAGE_FLOATS = 2 * BM * BK;               // A tile + B tile = 8192 floats
constexpr int DSMEM = STAGES * STAGE_FLOATS * 4;        // 96 KB

enum { EPI_FWD = 0, EPI_ERR = 1, EPI_UPD = 2 };

// fill one pipeline stage (A tile [BM][BK] + B tile [BN][BK], both K-major gmem)
__device__ __forceinline__ void fill_stage(uint32_t sbase, const float* __restrict__ A,
                                           const float* __restrict__ B, int K,
                                           int bm, int bn, int kt, int tid) {
    const float* Ag = A + (size_t)bm * K + (size_t)kt * BK;
    const float* Bg = B + (size_t)bn * K + (size_t)kt * BK;
#pragma unroll
    for (int i = 0; i < 4; i++) {
        const int c = tid + (i << 8);          // 0..1023 chunk id
        const int row = c >> 3;
        const int kc = (c & 7) << 2;           // k of chunk start
        const uint32_t d = sbase + ((uint32_t)swidx(row, kc) << 2);
        cp16(d, Ag + (size_t)row * K + kc);
    }
#pragma unroll
    for (int i = 0; i < 4; i++) {
        const int c = tid + (i << 8);
        const int row = c >> 3;
        const int kc = (c & 7) << 2;
        const uint32_t d = sbase + (uint32_t)(BM * BK * 4) + ((uint32_t)swidx(row, kc) << 2);
        cp16(d, Bg + (size_t)row * K + kc);
    }
    asm volatile("cp.async.commit_group;" ::: "memory");
}

// shared GEMM body: C(bm:bm+128, bn:bn+128) over K; A,B tf32-rounded, NT K-major.
template <int EPI>
__device__ __forceinline__ void gemm_body(float* smem, uint32_t sb,
                                          const float* __restrict__ A,
                                          const float* __restrict__ B,
                                          const float* __restrict__ X,
                                          float* __restrict__ C,
                                          float* __restrict__ Cr,
                                          int N, int K, int bm, int bn, int tid)
{
    const int wid = tid >> 5;
    const int lane = tid & 31;
    const int gr = lane >> 2;        // 0..7
    const int ct = lane & 3;         // 0..3
    const int wm = (wid & 3) * 32;   // 4 warps down
    const int wn = (wid >> 2) * 64;  // 2 warps across
    const int NT = K / BK;

    float acc[2][8][4];
#pragma unroll
    for (int mi = 0; mi < 2; mi++)
#pragma unroll
        for (int j = 0; j < 8; j++)
#pragma unroll
            for (int q = 0; q < 4; q++) acc[mi][j][q] = 0.0f;

    // prologue: stages 0,1
    fill_stage(sb + 0u * STAGE_FLOATS * 4, A, B, K, bm, bn, 0, tid);
    fill_stage(sb + 1u * STAGE_FLOATS * 4, A, B, K, bm, bn, 1, tid);

    int buf = 0;
    for (int kt = 0; kt < NT; kt++) {
        asm volatile("cp.async.wait_group 1;" ::: "memory");
        __syncthreads();

        const int nf = kt + 2;
        if (nf < NT) {
            int fb = buf + 2; if (fb >= STAGES) fb -= STAGES;
            fill_stage(sb + (uint32_t)fb * STAGE_FLOATS * 4, A, B, K, bm, bn, nf, tid);
        }

        const float* As_ = smem + buf * STAGE_FLOATS;
        const float* Bs_ = As_ + BM * BK;

#pragma unroll
        for (int k8 = 0; k8 < 4; k8++) {
            const int kb = k8 * 8;
            uint32_t afr[2][4];
            uint32_t bfr[8][2];
#pragma unroll
            for (int mi = 0; mi < 2; mi++) {
                const int r0 = wm + mi * 16 + gr;
                afr[mi][0] = __float_as_uint(As_[swidx(r0,     kb + ct)]);
                afr[mi][1] = __float_as_uint(As_[swidx(r0 + 8, kb + ct)]);
                afr[mi][2] = __float_as_uint(As_[swidx(r0,     kb + ct + 4)]);
                afr[mi][3] = __float_as_uint(As_[swidx(r0 + 8, kb + ct + 4)]);
            }
#pragma unroll
            for (int j = 0; j < 8; j++) {
                const int n0 = wn + j * 8 + gr;
                bfr[j][0] = __float_as_uint(Bs_[swidx(n0, kb + ct)]);
                bfr[j][1] = __float_as_uint(Bs_[swidx(n0, kb + ct + 4)]);
            }
#pragma unroll
            for (int mi = 0; mi < 2; mi++)
#pragma unroll
                for (int j = 0; j < 8; j++)
                    mma_tf32(acc[mi][j], afr[mi], bfr[j]);
        }

        buf++; if (buf >= STAGES) buf = 0;
    }

    // ---------------- epilogue ----------------
#pragma unroll
    for (int mi = 0; mi < 2; mi++) {
#pragma unroll
        for (int half = 0; half < 2; half++) {
            const int m = bm + wm + mi * 16 + gr + half * 8;
#pragma unroll
            for (int j = 0; j < 8; j++) {
                const int n = bn + wn + j * 8 + 2 * ct;
                const size_t off = (size_t)m * N + n;
                const float a0 = acc[mi][j][2 * half + 0];
                const float a1 = acc[mi][j][2 * half + 1];
                float v0, v1;
                if (EPI == EPI_FWD) {
                    v0 = tanhf(a0 + X[n]);
                    v1 = tanhf(a1 + X[n + 1]);
                } else if (EPI == EPI_ERR) {
                    const float2 xv = *(const float2*)(X + off);
                    v0 = xv.x - tanhf(a0);
                    v1 = xv.y - tanhf(a1);
                } else {  // EPI_UPD (covers UPD3 via X == C)
                    const float2 cv = *(const float2*)(C + off);
                    const float2 xv = *(const float2*)(X + off);
                    v0 = cv.x + LRATE * (a0 - xv.x);
                    v1 = cv.y + LRATE * (a1 - xv.y);
                }
                *(float2*)(C + off) = make_float2(v0, v1);
                *(float2*)(Cr + off) = make_float2(rnd_tf32(v0), rnd_tf32(v1));
            }
        }
    }
}

// single-GEMM kernel (forward pass: sequential dependency)
template <int EPI>
__global__ __launch_bounds__(256, 2)
void gemm_epi(const float* __restrict__ A, const float* __restrict__ B,
              const float* __restrict__ X, float* __restrict__ C,
              float* __restrict__ Cr, int N, int K)
{
    extern __shared__ float smem[];
    const uint32_t sb = (uint32_t)__cvta_generic_to_shared(smem);
    gemm_body<EPI>(smem, sb, A, B, X, C, Cr, N, K,
                   blockIdx.y * BM, blockIdx.x * BN, threadIdx.x);
}

// ---- fused 3-segment kernel: one launch covers 3 independent GEMMs ----
struct Seg {
    const float* A; const float* B; const float* X;
    float* C; float* Cr;
    int N, K, nbx, cta_end;   // cta_end = exclusive prefix sum of CTA counts
};

template <int EPI>
__global__ __launch_bounds__(256, 2)
void gemm_fused3(Seg s0, Seg s1, Seg s2)
{
    extern __shared__ float smem[];
    const uint32_t sb = (uint32_t)__cvta_generic_to_shared(smem);
    const int cta = blockIdx.x;

    Seg s;
    int start;
    if (cta < s0.cta_end)       { s = s0; start = 0; }
    else if (cta < s1.cta_end)  { s = s1; start = s0.cta_end; }
    else                        { s = s2; start = s1.cta_end; }

    const int loc = cta - start;
    const int bm = (loc / s.nbx) * BM;
    const int bn = (loc % s.nbx) * BN;
    gemm_body<EPI>(smem, sb, s.A, s.B, s.X, s.C, s.Cr, s.N, s.K, bm, bn, threadIdx.x);
}

// ---------------- prep / output helpers ----------------
__global__ void round_copy(const float* __restrict__ in, float* __restrict__ out, int n) {
    for (int i = blockIdx.x * blockDim.x + threadIdx.x; i < n; i += gridDim.x * blockDim.x)
        out[i] = rnd_tf32(in[i]);
}

// W (Nn,Kk) -> Wr (Nn,Kk) rounded, Wt (Kk,Nn) rounded-transpose
__global__ void trans_round(const float* __restrict__ W, float* __restrict__ Wr,
                            float* __restrict__ Wt, int Nn, int Kk) {
    __shared__ float t[32][33];
    const int k0 = blockIdx.x * 32;
    const int n0 = blockIdx.y * 32;
    const int tx = threadIdx.x;
    const int ty = threadIdx.y;  // 32x8
#pragma unroll
    for (int i = 0; i < 4; i++) {
        const int n = n0 + ty + i * 8;
        const float v = rnd_tf32(W[(size_t)n * Kk + k0 + tx]);
        Wr[(size_t)n * Kk + k0 + tx] = v;
        t[ty + i * 8][tx] = v;
    }
    __syncthreads();
#pragma unroll
    for (int i = 0; i < 4; i++) {
        const int k = k0 + ty + i * 8;
        Wt[(size_t)k * Nn + n0 + tx] = t[tx][ty + i * 8];
    }
}

__global__ void copy_kernel(float* __restrict__ dst, const float* __restrict__ src, int n) {
    for (int i = blockIdx.x * blockDim.x + threadIdx.x; i < n; i += gridDim.x * blockDim.x)
        dst[i] = src[i];
}

__global__ void zero1_kernel(float* p) { *p = 0.0f; }

__global__ void sumsq_kernel(const float* __restrict__ a, int n, float* out) {
    float s = 0.0f;
    for (int i = blockIdx.x * blockDim.x + threadIdx.x; i < n; i += gridDim.x * blockDim.x) {
        float v = a[i];
        s += v * v;
    }
#pragma unroll
    for (int o = 16; o > 0; o >>= 1) s += __shfl_xor_sync(0xFFFFFFFFu, s, o);
    __shared__ float ws[32];
    if ((threadIdx.x & 31) == 0) ws[threadIdx.x >> 5] = s;
    __syncthreads();
    if (threadIdx.x < 32) {
        s = (threadIdx.x < (blockDim.x >> 5)) ? ws[threadIdx.x] : 0.0f;
#pragma unroll
        for (int o = 16; o > 0; o >>= 1) s += __shfl_xor_sync(0xFFFFFFFFu, s, o);
        if (threadIdx.x == 0) atomicAdd(out, 0.5f * s);
    }
}

// ---------------- launcher ----------------
extern "C" void kernel_launch(void* const* d_in, const int* in_sizes, int n_in,
                              void* d_out, int out_size)
{
    const float* x  = (const float*)d_in[0];
    const float* W0 = (const float*)d_in[1];
    const float* b0 = (const float*)d_in[2];
    const float* W1 = (const float*)d_in[3];
    const float* b1 = (const float*)d_in[4];
    const float* W2 = (const float*)d_in[5];
    const float* b2 = (const float*)d_in[6];

    float *r1, *r2, *r3, *e0, *e1, *e2;
    float *r1r, *r2r, *r3r, *e0r, *e1r, *e2r, *xr;
    float *W0r, *W1r, *W2r, *W0t, *W1t, *W2t;
    cudaGetSymbolAddress((void**)&r1, g_r1);
    cudaGetSymbolAddress((void**)&r2, g_r2);
    cudaGetSymbolAddress((void**)&r3, g_r3);
    cudaGetSymbolAddress((void**)&e0, g_e0);
    cudaGetSymbolAddress((void**)&e1, g_e1);
    cudaGetSymbolAddress((void**)&e2, g_e2);
    cudaGetSymbolAddress((void**)&r1r, g_r1r);
    cudaGetSymbolAddress((void**)&r2r, g_r2r);
    cudaGetSymbolAddress((void**)&r3r, g_r3r);
    cudaGetSymbolAddress((void**)&e0r, g_e0r);
    cudaGetSymbolAddress((void**)&e1r, g_e1r);
    cudaGetSymbolAddress((void**)&e2r, g_e2r);
    cudaGetSymbolAddress((void**)&xr, g_xr);
    cudaGetSymbolAddress((void**)&W0r, g_W0r);
    cudaGetSymbolAddress((void**)&W1r, g_W1r);
    cudaGetSymbolAddress((void**)&W2r, g_W2r);
    cudaGetSymbolAddress((void**)&W0t, g_W0t);
    cudaGetSymbolAddress((void**)&W1t, g_W1t);
    cudaGetSymbolAddress((void**)&W2t, g_W2t);

    cudaFuncSetAttribute(gemm_epi<EPI_FWD>, cudaFuncAttributeMaxDynamicSharedMemorySize, DSMEM);
    cudaFuncSetAttribute(gemm_fused3<EPI_ERR>, cudaFuncAttributeMaxDynamicSharedMemorySize, DSMEM);
    cudaFuncSetAttribute(gemm_fused3<EPI_UPD>, cudaFuncAttributeMaxDynamicSharedMemorySize, DSMEM);

    // ---- prep: round operands to nearest-tf32; transpose weights ----
    round_copy<<<512, 256>>>(x, xr, BATCH * D0);
    {
        dim3 b(32, 8);
        trans_round<<<dim3(D0 / 32, D1 / 32), b>>>(W0, W0r, W0t, D1, D0);
        trans_round<<<dim3(D1 / 32, D2 / 32), b>>>(W1, W1r, W1t, D2, D1);
        trans_round<<<dim3(D2 / 32, D3 / 32), b>>>(W2, W2r, W2t, D3, D2);
    }

    const dim3 blk(256);
    const dim3 gD1(D1 / BN, BATCH / BM);
    const dim3 gD2(D2 / BN, BATCH / BM);
    const dim3 gD3(D3 / BN, BATCH / BM);

    // segment CTA counts
    const int MB = BATCH / BM;                       // 32
    const int c_e1 = (D1 / BN) * MB;                 // 512  (K=D2=2048)
    const int c_e0 = (D0 / BN) * MB;                 // 256  (K=D1=2048)
    const int c_e2 = (D2 / BN) * MB;                 // 512  (K=D3=512)
    const int c_r2 = (D2 / BN) * MB;                 // 512  (K=D1=2048)
    const int c_r3 = (D3 / BN) * MB;                 // 128  (K=D2=2048)
    const int c_r1 = (D1 / BN) * MB;                 // 512  (K=D0=1024)

    // ERR group: order long-K first so short-K backfills the tail
    Seg E0 = { r2r, W1t, r1, e1, e1r, D1, D2, D1 / BN, c_e1 };
    Seg E1 = { r1r, W0t, x,  e0, e0r, D0, D1, D0 / BN, c_e1 + c_e0 };
    Seg E2 = { r3r, W2t, r2, e2, e2r, D2, D3, D2 / BN, c_e1 + c_e0 + c_e2 };
    const int nERR = c_e1 + c_e0 + c_e2;

    // UPD group (UPD3 expressed as UPD with X == C == r3)
    Seg U0 = { e1r, W1r, e2, r2, r2r, D2, D1, D2 / BN, c_r2 };
    Seg U1 = { e2r, W2r, r3, r3, r3r, D3, D2, D3 / BN, c_r2 + c_r3 };
    Seg U2 = { e0r, W0r, e1, r1, r1r, D1, D0, D1 / BN, c_r2 + c_r3 + c_r1 };
    const int nUPD = c_r2 + c_r3 + c_r1;

    // ---- forward init: r[i+1] = tanh(r[i] @ W_i^T + b_i) ----
    gemm_epi<EPI_FWD><<<gD1, blk, DSMEM>>>(xr,  W0r, b0, r1, r1r, D1, D0);
    gemm_epi<EPI_FWD><<<gD2, blk, DSMEM>>>(r1r, W1r, b1, r2, r2r, D2, D1);
    gemm_epi<EPI_FWD><<<gD3, blk, DSMEM>>>(r2r, W2r, b2, r3, r3r, D3, D2);

    // ---- relaxation steps: 2 fused launches per step ----
    for (int s = 0; s < NSTEPS; s++) {
        gemm_fused3<EPI_ERR><<<nERR, blk, DSMEM>>>(E0, E1, E2);
        gemm_fused3<EPI_UPD><<<nUPD, blk, DSMEM>>>(U0, U1, U2);
    }

    // ---- final errors for energy ----
    gemm_fused3<EPI_ERR><<<nERR, blk, DSMEM>>>(E0, E1, E2);

    // ---- outputs: r3 flattened, then scalar total_error ----
    float* out = (float*)d_out;
    const int n_r3 = BATCH * D3;
    int ncopy = out_size < n_r3 ? out_size : n_r3;
    copy_kernel<<<2048, 256>>>(out, r3, ncopy);

    if (out_size > n_r3) {
        float* esc = out + n_r3;
        zero1_kernel<<<1, 1>>>(esc);
        sumsq_kernel<<<296, 256>>>(e0, BATCH * D0, esc);
        sumsq_kernel<<<296, 256>>>(e1, BATCH * D1, esc);
        sumsq_kernel<<<296, 256>>>(e2, BATCH * D2, esc);
        sumsq_kernel<<<296, 256>>>(r3, BATCH * D3, esc);
    }
}

// round 11
// speedup vs baseline: 3.9533x; 1.0538x over previous
#include <cuda_runtime.h>
#include <cstdint>

#define BATCH 4096
#define D0 1024
#define D1 2048
#define D2 2048
#define D3 512
#define NSTEPS 20
#define LRATE 0.1f

// ---------------- device scratch (allocation-free rule: __device__ globals) ----
__device__ __align__(128) float g_r1[BATCH * D1];
__device__ __align__(128) float g_r2[BATCH * D2];
__device__ __align__(128) float g_r3[BATCH * D3];
__device__ __align__(128) float g_e0[BATCH * D0];
__device__ __align__(128) float g_e1[BATCH * D1];
__device__ __align__(128) float g_e2[BATCH * D2];
// tf32-rounded twins (GEMM operands only)
__device__ __align__(128) float g_r1r[BATCH * D1];
__device__ __align__(128) float g_r2r[BATCH * D2];
__device__ __align__(128) float g_r3r[BATCH * D3];
__device__ __align__(128) float g_e0r[BATCH * D0];
__device__ __align__(128) float g_e1r[BATCH * D1];
__device__ __align__(128) float g_e2r[BATCH * D2];
__device__ __align__(128) float g_xr[BATCH * D0];
// rounded weights + rounded transposes (so every GEMM is NT, K-major B)
__device__ __align__(128) float g_W0r[D1 * D0];
__device__ __align__(128) float g_W1r[D2 * D1];
__device__ __align__(128) float g_W2r[D3 * D2];
__device__ __align__(128) float g_W0t[D0 * D1];
__device__ __align__(128) float g_W1t[D1 * D2];
__device__ __align__(128) float g_W2t[D2 * D3];
// double-precision energy accumulator
__device__ double g_esum;

// ---------------- helpers ----------------
__device__ __forceinline__ float rnd_tf32(float x) {
    float y;
    asm("cvt.rna.tf32.f32 %0, %1;" : "=f"(y) : "f"(x));
    return y;
}

__device__ __forceinline__ void mma_tf32(float* c, const uint32_t* a, const uint32_t* b) {
    asm volatile(
        "mma.sync.aligned.m16n8k8.row.col.f32.tf32.tf32.f32 "
        "{%0,%1,%2,%3}, {%4,%5,%6,%7}, {%8,%9}, {%0,%1,%2,%3};"
        : "+f"(c[0]), "+f"(c[1]), "+f"(c[2]), "+f"(c[3])
        : "r"(a[0]), "r"(a[1]), "r"(a[2]), "r"(a[3]), "r"(b[0]), "r"(b[1]));
}

__device__ __forceinline__ void cp16(uint32_t s, const void* g) {
    asm volatile("cp.async.cg.shared.global [%0], [%1], 16;" :: "r"(s), "l"(g));
}

// swizzled float index for element (row, k) in a [128][32] tile
__device__ __forceinline__ int swidx(int row, int k) {
    return (row * 32 + k) ^ ((row & 7) << 2);
}

// ---------------- GEMM config ----------------
constexpr int BM = 128, BN = 128, BK = 32;
constexpr int STAGES = 3;
constexpr int STAGE_FLOATS = 2 * BM * BK;               // A tile + B tile = 8192 floats
constexpr int DSMEM = STAGES * STAGE_FLOATS * 4;        // 96 KB

enum { EPI_FWD = 0, EPI_ERR = 1, EPI_UPD = 2 };

// fill one pipeline stage (A tile [BM][BK] + B tile [BN][BK], both K-major gmem)
__device__ __forceinline__ void fill_stage(uint32_t sbase, const float* __restrict__ A,
                                           const float* __restrict__ B, int K,
                                           int bm, int bn, int kt, int tid) {
    const float* Ag = A + (size_t)bm * K + (size_t)kt * BK;
    const float* Bg = B + (size_t)bn * K + (size_t)kt * BK;
#pragma unroll
    for (int i = 0; i < 4; i++) {
        const int c = tid + (i << 8);          // 0..1023 chunk id
        const int row = c >> 3;
        const int kc = (c & 7) << 2;           // k of chunk start
        const uint32_t d = sbase + ((uint32_t)swidx(row, kc) << 2);
        cp16(d, Ag + (size_t)row * K + kc);
    }
#pragma unroll
    for (int i = 0; i < 4; i++) {
        const int c = tid + (i << 8);
        const int row = c >> 3;
        const int kc = (c & 7) << 2;
        const uint32_t d = sbase + (uint32_t)(BM * BK * 4) + ((uint32_t)swidx(row, kc) << 2);
        cp16(d, Bg + (size_t)row * K + kc);
    }
    asm volatile("cp.async.commit_group;" ::: "memory");
}

// shared GEMM body: C(bm:bm+128, bn:bn+128) over K; A,B tf32-rounded, NT K-major.
// Writes full C and rounded twin Cr. If EPI_ERR and esum != nullptr, also
// accumulates sum(C^2) of this tile into *esum (double atomicAdd per CTA).
template <int EPI>
__device__ __forceinline__ void gemm_body(float* smem, uint32_t sb,
                                          const float* __restrict__ A,
                                          const float* __restrict__ B,
                                          const float* __restrict__ X,
                                          float* __restrict__ C,
                                          float* __restrict__ Cr,
                                          double* esum,
                                          int N, int K, int bm, int bn, int tid)
{
    const int wid = tid >> 5;
    const int lane = tid & 31;
    const int gr = lane >> 2;        // 0..7
    const int ct = lane & 3;         // 0..3
    const int wm = (wid & 3) * 32;   // 4 warps down
    const int wn = (wid >> 2) * 64;  // 2 warps across
    const int NT = K / BK;

    float acc[2][8][4];
#pragma unroll
    for (int mi = 0; mi < 2; mi++)
#pragma unroll
        for (int j = 0; j < 8; j++)
#pragma unroll
            for (int q = 0; q < 4; q++) acc[mi][j][q] = 0.0f;

    // prologue: stages 0,1
    fill_stage(sb + 0u * STAGE_FLOATS * 4, A, B, K, bm, bn, 0, tid);
    fill_stage(sb + 1u * STAGE_FLOATS * 4, A, B, K, bm, bn, 1, tid);

    int buf = 0;
    for (int kt = 0; kt < NT; kt++) {
        asm volatile("cp.async.wait_group 1;" ::: "memory");
        __syncthreads();

        const int nf = kt + 2;
        if (nf < NT) {
            int fb = buf + 2; if (fb >= STAGES) fb -= STAGES;
            fill_stage(sb + (uint32_t)fb * STAGE_FLOATS * 4, A, B, K, bm, bn, nf, tid);
        }

        const float* As_ = smem + buf * STAGE_FLOATS;
        const float* Bs_ = As_ + BM * BK;

#pragma unroll
        for (int k8 = 0; k8 < 4; k8++) {
            const int kb = k8 * 8;
            uint32_t afr[2][4];
            uint32_t bfr[8][2];
#pragma unroll
            for (int mi = 0; mi < 2; mi++) {
                const int r0 = wm + mi * 16 + gr;
                afr[mi][0] = __float_as_uint(As_[swidx(r0,     kb + ct)]);
                afr[mi][1] = __float_as_uint(As_[swidx(r0 + 8, kb + ct)]);
                afr[mi][2] = __float_as_uint(As_[swidx(r0,     kb + ct + 4)]);
                afr[mi][3] = __float_as_uint(As_[swidx(r0 + 8, kb + ct + 4)]);
            }
#pragma unroll
            for (int j = 0; j < 8; j++) {
                const int n0 = wn + j * 8 + gr;
                bfr[j][0] = __float_as_uint(Bs_[swidx(n0, kb + ct)]);
                bfr[j][1] = __float_as_uint(Bs_[swidx(n0, kb + ct + 4)]);
            }
#pragma unroll
            for (int mi = 0; mi < 2; mi++)
#pragma unroll
                for (int j = 0; j < 8; j++)
                    mma_tf32(acc[mi][j], afr[mi], bfr[j]);
        }

        buf++; if (buf >= STAGES) buf = 0;
    }

    // ---------------- epilogue ----------------
    float ssq = 0.0f;
#pragma unroll
    for (int mi = 0; mi < 2; mi++) {
#pragma unroll
        for (int half = 0; half < 2; half++) {
            const int m = bm + wm + mi * 16 + gr + half * 8;
#pragma unroll
            for (int j = 0; j < 8; j++) {
                const int n = bn + wn + j * 8 + 2 * ct;
                const size_t off = (size_t)m * N + n;
                const float a0 = acc[mi][j][2 * half + 0];
                const float a1 = acc[mi][j][2 * half + 1];
                float v0, v1;
                if (EPI == EPI_FWD) {
                    v0 = tanhf(a0 + X[n]);
                    v1 = tanhf(a1 + X[n + 1]);
                } else if (EPI == EPI_ERR) {
                    const float2 xv = *(const float2*)(X + off);
                    v0 = xv.x - tanhf(a0);
                    v1 = xv.y - tanhf(a1);
                } else {  // EPI_UPD (covers UPD3 via X == C)
                    const float2 cv = *(const float2*)(C + off);
                    const float2 xv = *(const float2*)(X + off);
                    v0 = cv.x + LRATE * (a0 - xv.x);
                    v1 = cv.y + LRATE * (a1 - xv.y);
                }
                *(float2*)(C + off) = make_float2(v0, v1);
                *(float2*)(Cr + off) = make_float2(rnd_tf32(v0), rnd_tf32(v1));
                if (EPI == EPI_ERR) ssq += v0 * v0 + v1 * v1;
            }
        }
    }

    if (EPI == EPI_ERR && esum != nullptr) {
#pragma unroll
        for (int o = 16; o > 0; o >>= 1) ssq += __shfl_xor_sync(0xFFFFFFFFu, ssq, o);
        __syncthreads();  // stage buffers no longer needed; reuse smem for reduction
        if (lane == 0) smem[wid] = ssq;
        __syncthreads();
        if (tid == 0) {
            float s = 0.0f;
#pragma unroll
            for (int w = 0; w < 8; w++) s += smem[w];
            atomicAdd(esum, (double)s);
        }
    }
}

// single-GEMM kernel (forward pass: sequential dependency)
template <int EPI>
__global__ __launch_bounds__(256, 2)
void gemm_epi(const float* __restrict__ A, const float* __restrict__ B,
              const float* __restrict__ X, float* __restrict__ C,
              float* __restrict__ Cr, int N, int K)
{
    extern __shared__ float smem[];
    const uint32_t sb = (uint32_t)__cvta_generic_to_shared(smem);
    gemm_body<EPI>(smem, sb, A, B, X, C, Cr, nullptr, N, K,
                   blockIdx.y * BM, blockIdx.x * BN, threadIdx.x);
}

// ---- fused 3-segment kernel: one launch covers 3 independent GEMMs ----
struct Seg {
    const float* A; const float* B; const float* X;
    float* C; float* Cr;
    int N, K, nbx, cta_end;   // cta_end = exclusive prefix sum of CTA counts
};

template <int EPI>
__global__ __launch_bounds__(256, 2)
void gemm_fused3(Seg s0, Seg s1, Seg s2, double* esum)
{
    extern __shared__ float smem[];
    const uint32_t sb = (uint32_t)__cvta_generic_to_shared(smem);
    const int cta = blockIdx.x;

    Seg s;
    int start;
    if (cta < s0.cta_end)       { s = s0; start = 0; }
    else if (cta < s1.cta_end)  { s = s1; start = s0.cta_end; }
    else                        { s = s2; start = s1.cta_end; }

    const int loc = cta - start;
    const int bm = (loc / s.nbx) * BM;
    const int bn = (loc % s.nbx) * BN;
    gemm_body<EPI>(smem, sb, s.A, s.B, s.X, s.C, s.Cr, esum, s.N, s.K, bm, bn, threadIdx.x);
}

// ---------------- prep / output helpers ----------------
__global__ void round_copy(const float* __restrict__ in, float* __restrict__ out, int n) {
    for (int i = blockIdx.x * blockDim.x + threadIdx.x; i < n; i += gridDim.x * blockDim.x)
        out[i] = rnd_tf32(in[i]);
}

// W (Nn,Kk) -> Wr (Nn,Kk) rounded, Wt (Kk,Nn) rounded-transpose
__global__ void trans_round(const float* __restrict__ W, float* __restrict__ Wr,
                            float* __restrict__ Wt, int Nn, int Kk) {
    __shared__ float t[32][33];
    const int k0 = blockIdx.x * 32;
    const int n0 = blockIdx.y * 32;
    const int tx = threadIdx.x;
    const int ty = threadIdx.y;  // 32x8
#pragma unroll
    for (int i = 0; i < 4; i++) {
        const int n = n0 + ty + i * 8;
        const float v = rnd_tf32(W[(size_t)n * Kk + k0 + tx]);
        Wr[(size_t)n * Kk + k0 + tx] = v;
        t[ty + i * 8][tx] = v;
    }
    __syncthreads();
#pragma unroll
    for (int i = 0; i < 4; i++) {
        const int k = k0 + ty + i * 8;
        Wt[(size_t)k * Nn + n0 + tx] = t[tx][ty + i * 8];
    }
}

__global__ void zero_dbl_kernel(double* p) { *p = 0.0; }

// copy r3 -> out while accumulating sum(r3^2) into the double accumulator
__global__ void copy_ssq_kernel(float* __restrict__ dst, const float* __restrict__ src,
                                int n, double* esum) {
    float s = 0.0f;
    for (int i = blockIdx.x * blockDim.x + threadIdx.x; i < n; i += gridDim.x * blockDim.x) {
        const float v = src[i];
        dst[i] = v;
        s += v * v;
    }
#pragma unroll
    for (int o = 16; o > 0; o >>= 1) s += __shfl_xor_sync(0xFFFFFFFFu, s, o);
    __shared__ float ws[32];
    if ((threadIdx.x & 31) == 0) ws[threadIdx.x >> 5] = s;
    __syncthreads();
    if (threadIdx.x < 32) {
        s = (threadIdx.x < (blockDim.x >> 5)) ? ws[threadIdx.x] : 0.0f;
#pragma unroll
        for (int o = 16; o > 0; o >>= 1) s += __shfl_xor_sync(0xFFFFFFFFu, s, o);
        if (threadIdx.x == 0) atomicAdd(esum, (double)s);
    }
}

__global__ void finalize_kernel(const double* esum, float* out) {
    *out = (float)(0.5 * *esum);
}

// ---------------- launcher ----------------
extern "C" void kernel_launch(void* const* d_in, const int* in_sizes, int n_in,
                              void* d_out, int out_size)
{
    const float* x  = (const float*)d_in[0];
    const float* W0 = (const float*)d_in[1];
    const float* b0 = (const float*)d_in[2];
    const float* W1 = (const float*)d_in[3];
    const float* b1 = (const float*)d_in[4];
    const float* W2 = (const float*)d_in[5];
    const float* b2 = (const float*)d_in[6];

    float *r1, *r2, *r3, *e0, *e1, *e2;
    float *r1r, *r2r, *r3r, *e0r, *e1r, *e2r, *xr;
    float *W0r, *W1r, *W2r, *W0t, *W1t, *W2t;
    double* esum;
    cudaGetSymbolAddress((void**)&r1, g_r1);
    cudaGetSymbolAddress((void**)&r2, g_r2);
    cudaGetSymbolAddress((void**)&r3, g_r3);
    cudaGetSymbolAddress((void**)&e0, g_e0);
    cudaGetSymbolAddress((void**)&e1, g_e1);
    cudaGetSymbolAddress((void**)&e2, g_e2);
    cudaGetSymbolAddress((void**)&r1r, g_r1r);
    cudaGetSymbolAddress((void**)&r2r, g_r2r);
    cudaGetSymbolAddress((void**)&r3r, g_r3r);
    cudaGetSymbolAddress((void**)&e0r, g_e0r);
    cudaGetSymbolAddress((void**)&e1r, g_e1r);
    cudaGetSymbolAddress((void**)&e2r, g_e2r);
    cudaGetSymbolAddress((void**)&xr, g_xr);
    cudaGetSymbolAddress((void**)&W0r, g_W0r);
    cudaGetSymbolAddress((void**)&W1r, g_W1r);
    cudaGetSymbolAddress((void**)&W2r, g_W2r);
    cudaGetSymbolAddress((void**)&W0t, g_W0t);
    cudaGetSymbolAddress((void**)&W1t, g_W1t);
    cudaGetSymbolAddress((void**)&W2t, g_W2t);
    cudaGetSymbolAddress((void**)&esum, g_esum);

    cudaFuncSetAttribute(gemm_epi<EPI_FWD>, cudaFuncAttributeMaxDynamicSharedMemorySize, DSMEM);
    cudaFuncSetAttribute(gemm_fused3<EPI_ERR>, cudaFuncAttributeMaxDynamicSharedMemorySize, DSMEM);
    cudaFuncSetAttribute(gemm_fused3<EPI_UPD>, cudaFuncAttributeMaxDynamicSharedMemorySize, DSMEM);

    // ---- prep: round operands to nearest-tf32; transpose weights ----
    round_copy<<<512, 256>>>(x, xr, BATCH * D0);
    {
        dim3 b(32, 8);
        trans_round<<<dim3(D0 / 32, D1 / 32), b>>>(W0, W0r, W0t, D1, D0);
        trans_round<<<dim3(D1 / 32, D2 / 32), b>>>(W1, W1r, W1t, D2, D1);
        trans_round<<<dim3(D2 / 32, D3 / 32), b>>>(W2, W2r, W2t, D3, D2);
    }

    const dim3 blk(256);
    const dim3 gD1(D1 / BN, BATCH / BM);
    const dim3 gD2(D2 / BN, BATCH / BM);
    const dim3 gD3(D3 / BN, BATCH / BM);

    // segment CTA counts
    const int MB = BATCH / BM;                       // 32
    const int c_e1 = (D1 / BN) * MB;                 // 512  (K=D2=2048)
    const int c_e0 = (D0 / BN) * MB;                 // 256  (K=D1=2048)
    const int c_e2 = (D2 / BN) * MB;                 // 512  (K=D3=512)
    const int c_r2 = (D2 / BN) * MB;                 // 512  (K=D1=2048)
    const int c_r3 = (D3 / BN) * MB;                 // 128  (K=D2=2048)
    const int c_r1 = (D1 / BN) * MB;                 // 512  (K=D0=1024)

    // ERR group: order long-K first so short-K backfills the tail
    Seg E0 = { r2r, W1t, r1, e1, e1r, D1, D2, D1 / BN, c_e1 };
    Seg E1 = { r1r, W0t, x,  e0, e0r, D0, D1, D0 / BN, c_e1 + c_e0 };
    Seg E2 = { r3r, W2t, r2, e2, e2r, D2, D3, D2 / BN, c_e1 + c_e0 + c_e2 };
    const int nERR = c_e1 + c_e0 + c_e2;

    // UPD group (UPD3 expressed as UPD with X == C == r3)
    Seg U0 = { e1r, W1r, e2, r2, r2r, D2, D1, D2 / BN, c_r2 };
    Seg U1 = { e2r, W2r, r3, r3, r3r, D3, D2, D3 / BN, c_r2 + c_r3 };
    Seg U2 = { e0r, W0r, e1, r1, r1r, D1, D0, D1 / BN, c_r2 + c_r3 + c_r1 };
    const int nUPD = c_r2 + c_r3 + c_r1;

    // ---- forward init: r[i+1] = tanh(r[i] @ W_i^T + b_i) ----
    gemm_epi<EPI_FWD><<<gD1, blk, DSMEM>>>(xr,  W0r, b0, r1, r1r, D1, D0);
    gemm_epi<EPI_FWD><<<gD2, blk, DSMEM>>>(r1r, W1r, b1, r2, r2r, D2, D1);
    gemm_epi<EPI_FWD><<<gD3, blk, DSMEM>>>(r2r, W2r, b2, r3, r3r, D3, D2);

    // ---- relaxation steps: 2 fused launches per step ----
    for (int s = 0; s < NSTEPS; s++) {
        gemm_fused3<EPI_ERR><<<nERR, blk, DSMEM>>>(E0, E1, E2, nullptr);
        gemm_fused3<EPI_UPD><<<nUPD, blk, DSMEM>>>(U0, U1, U2, nullptr);
    }

    // ---- final errors + fused energy accumulation (fp64 accumulator) ----
    float* out = (float*)d_out;
    const int n_r3 = BATCH * D3;
    const bool want_energy = (out_size > n_r3);

    if (want_energy) zero_dbl_kernel<<<1, 1>>>(esum);
    gemm_fused3<EPI_ERR><<<nERR, blk, DSMEM>>>(E0, E1, E2, want_energy ? esum : nullptr);

    // ---- outputs: r3 flattened (+ ssq into esum), then scalar total_error ----
    int ncopy = out_size < n_r3 ? out_size : n_r3;
    copy_ssq_kernel<<<296, 256>>>(out, r3, ncopy, esum);

    if (want_energy) {
        finalize_kernel<<<1, 1>>>(esum, out + n_r3);
    }
}